// round 7
// baseline (speedup 1.0000x reference)
#include <cuda_runtime.h>
#include <cuda_bf16.h>
#include <math.h>

// Problem constants
#define LL 12
#define BB 8
#define HH 16
#define DD 64
#define EE 1024
#define FF 4096
#define VV 50257
#define TT 1023
#define SS 1024

// Split configs
#define QS 32   // qkv splits (K=1024/32)
#define FS 32   // fc splits
#define AS 32   // attnproj splits
#define MS 64   // mlpproj splits (K=4096/64)
#define TS 4    // attention T splits

// ---------------- scratch (static device, no allocation) ----------------
__device__ __align__(16) float g_h[BB * EE];
__device__ __align__(16) float g_x[BB * EE];
__device__ __align__(16) float g_qkv[QS * BB * 3 * EE];
__device__ __align__(16) float g_ap[BB * HH * TS * 66];   // [bh][ts][m,den,64 vals]
__device__ __align__(16) float g_aproj[AS * BB * EE];
__device__ __align__(16) float g_fc[FS * BB * FF];
__device__ __align__(16) float g_mp[MS * BB * EE];
__device__ __align__(16) float g_logits[BB * VV];
__device__ __align__(16) float g_stats[BB * 2];

// Scratch selection happens in DEVICE code only — passing __device__ symbols
// as kernel arguments from host code yields a bogus address (root cause of R5).
#define BUF_QKV   0
#define BUF_APROJ 1
#define BUF_FC    2
#define BUF_MP    3
template<int ID>
__device__ __forceinline__ float* scratch_buf() {
    if (ID == BUF_QKV)   return g_qkv;
    if (ID == BUF_APROJ) return g_aproj;
    if (ID == BUF_FC)    return g_fc;
    return g_mp;
}

// ---------------- reductions (256 threads) ----------------
__device__ __forceinline__ float blockReduceSum(float v, float* red) {
    #pragma unroll
    for (int o = 16; o; o >>= 1) v += __shfl_down_sync(0xffffffffu, v, o);
    int tid = threadIdx.x;
    if ((tid & 31) == 0) red[tid >> 5] = v;
    __syncthreads();
    if (tid == 0) {
        float s = red[0];
        #pragma unroll
        for (int i = 1; i < 8; i++) s += red[i];
        red[0] = s;
    }
    __syncthreads();
    float r = red[0];
    __syncthreads();
    return r;
}

__device__ __forceinline__ float blockReduceMax(float v, float* red) {
    #pragma unroll
    for (int o = 16; o; o >>= 1) v = fmaxf(v, __shfl_down_sync(0xffffffffu, v, o));
    int tid = threadIdx.x;
    if ((tid & 31) == 0) red[tid >> 5] = v;
    __syncthreads();
    if (tid == 0) {
        float s = red[0];
        #pragma unroll
        for (int i = 1; i < 8; i++) s = fmaxf(s, red[i]);
        red[0] = s;
    }
    __syncthreads();
    float r = red[0];
    __syncthreads();
    return r;
}

// ---------------- embed + ln1(layer 0) ----------------
__global__ void embed_kernel(const int* __restrict__ ids,
                             const float* __restrict__ wte,
                             const float* __restrict__ wpe,
                             const float* __restrict__ lw,
                             const float* __restrict__ lb) {
    __shared__ float s[EE];
    __shared__ float red[8];
    int b = blockIdx.x, tid = threadIdx.x;
    int id = ids[b * SS + (SS - 1)];
    for (int e = tid; e < EE; e += 256) {
        float v = wte[(size_t)id * EE + e] + wpe[(size_t)(SS - 1) * EE + e];
        s[e] = v;
        g_h[b * EE + e] = v;
    }
    __syncthreads();
    float ls = 0.f;
    for (int e = tid; e < EE; e += 256) ls += s[e];
    float mean = blockReduceSum(ls, red) * (1.f / EE);
    ls = 0.f;
    for (int e = tid; e < EE; e += 256) { float d = s[e] - mean; ls += d * d; }
    float rstd = rsqrtf(blockReduceSum(ls, red) * (1.f / EE) + 1e-5f);
    for (int e = tid; e < EE; e += 256)
        g_x[b * EE + e] = (s[e] - mean) * rstd * lw[e] + lb[e];
}

// ---------------- GEMV core: 8-batch split-K partial, float2 columns ----------------
template<int KC, int N>
__device__ __forceinline__ void gemv_core(const float* xs,
                                          const float* __restrict__ W,
                                          float* __restrict__ part) {
    int tid = threadIdx.x;
    int k0 = blockIdx.y * KC;
    int n2 = blockIdx.x * 256 + tid;                // float2 column index
    const float2* wp = ((const float2*)W) + (size_t)k0 * (N / 2) + n2;
    float2 acc[8];
    #pragma unroll
    for (int b = 0; b < 8; b++) { acc[b].x = 0.f; acc[b].y = 0.f; }
    #pragma unroll 8
    for (int k = 0; k < KC; k++) {
        float2 wv = wp[(size_t)k * (N / 2)];
        #pragma unroll
        for (int b = 0; b < 8; b++) {
            float xv = xs[b * KC + k];
            acc[b].x = fmaf(xv, wv.x, acc[b].x);
            acc[b].y = fmaf(xv, wv.y, acc[b].y);
        }
    }
    float2* p2 = (float2*)part;
    int sp = blockIdx.y;
    #pragma unroll
    for (int b = 0; b < 8; b++)
        p2[(size_t)(sp * 8 + b) * (N / 2) + n2] = acc[b];
}

// plain: input = g_x, output = scratch_buf<DST>
template<int KC, int N, int K, int DST>
__global__ void gemv_k(const float* __restrict__ W) {
    __shared__ float xs[8 * KC];
    int tid = threadIdx.x;
    int k0 = blockIdx.y * KC;
    for (int i = tid; i < 8 * KC; i += 256) {
        int b = i / KC, k = i % KC;
        xs[i] = g_x[b * K + k0 + k];
    }
    __syncthreads();
    gemv_core<KC, N>(xs, W, scratch_buf<DST>());
}

// gelu: input = sum of fc partials + bias, gelu'd  (K = FF)
template<int KC, int N, int DST>
__global__ void gemv_gelu_k(const float* __restrict__ fcb,
                            const float* __restrict__ W) {
    __shared__ float xs[8 * KC];
    int tid = threadIdx.x;
    int k0 = blockIdx.y * KC;
    for (int i = tid; i < 8 * KC; i += 256) {
        int b = i / KC, k = k0 + i % KC;
        float v = fcb[k];
        #pragma unroll 8
        for (int s = 0; s < FS; s++) v += g_fc[(size_t)(s * 8 + b) * FF + k];
        float c3 = v * v * v;
        xs[i] = 0.5f * v * (1.f + tanhf(0.7978845608028654f * (v + 0.044715f * c3)));
    }
    __syncthreads();
    gemv_core<KC, N>(xs, W, scratch_buf<DST>());
}

// ctx: input built from attention partials (flash-decode combine), K = EE
template<int KC, int N, int DST>
__global__ void gemv_ctx_k(const float* __restrict__ W) {
    __shared__ float xs[8 * KC];   // KC=32 -> 256 entries, 1 per thread
    int tid = threadIdx.x;
    int k0 = blockIdx.y * KC;
    {
        int b = tid / KC;
        int kg = k0 + tid % KC;
        int head = kg >> 6, d = kg & 63;
        int bh = b * HH + head;
        const float* ap = &g_ap[(size_t)bh * TS * 66];
        float gm = -1e30f;
        #pragma unroll
        for (int ts = 0; ts < TS; ts++) gm = fmaxf(gm, ap[ts * 66]);
        float den = 0.f, val = 0.f;
        #pragma unroll
        for (int ts = 0; ts < TS; ts++) {
            float e = __expf(ap[ts * 66] - gm);
            den += ap[ts * 66 + 1] * e;
            val += ap[ts * 66 + 2 + d] * e;
        }
        xs[tid] = val / den;
    }
    __syncthreads();
    gemv_core<KC, N>(xs, W, scratch_buf<DST>());
}

// ---------------- attention (flash-decode, split over T) ----------------
__global__ void attn_kernel(const float* __restrict__ kc,   // layer-offset k cache
                            const float* __restrict__ vc,
                            const float* __restrict__ cab,  // layer-offset qkv bias
                            const float* __restrict__ abp)  // &attn_bias[l]
{
    __shared__ __align__(16) float q[DD], kn[DD], vn[DD];
    __shared__ float sc[256];
    __shared__ float red[8];
    __shared__ __align__(16) float cp[8][DD];
    int tid = threadIdx.x;
    int bh = blockIdx.x;
    int b = bh >> 4, h = bh & 15;
    int ts = blockIdx.y;

    if (tid < 192) {
        int grp = tid >> 6;         // 0:q 1:k 2:v
        int d = tid & 63;
        int j = grp * EE + h * DD + d;
        float v = cab[j];
        #pragma unroll 8
        for (int s = 0; s < QS; s++) v += g_qkv[(size_t)(s * 8 + b) * (3 * EE) + j];
        if (grp == 0) q[d] = v; else if (grp == 1) kn[d] = v; else vn[d] = v;
    }
    __syncthreads();

    float abias = abp[0];
    int w = tid >> 5, lane = tid & 31;
    int t0 = ts * 256;
    float qa = q[2 * lane], qb = q[2 * lane + 1];

    #pragma unroll 4
    for (int i = w; i < 256; i += 8) {
        int t = t0 + i;
        const float* kr = (t < TT) ? (kc + ((size_t)(b * HH + h) * TT + t) * DD) : kn;
        float2 kk = ((const float2*)kr)[lane];
        float p = kk.x * qa + kk.y * qb;
        #pragma unroll
        for (int o = 16; o; o >>= 1) p += __shfl_down_sync(0xffffffffu, p, o);
        if (lane == 0) sc[i] = p * 0.125f + abias;
    }
    __syncthreads();

    float m = blockReduceMax(sc[tid], red);
    float e = __expf(sc[tid] - m);
    sc[tid] = e;
    float den = blockReduceSum(e, red);   // internal syncs also publish sc[]

    float2 acc; acc.x = 0.f; acc.y = 0.f;
    #pragma unroll 4
    for (int i = w; i < 256; i += 8) {
        int t = t0 + i;
        const float* vr = (t < TT) ? (vc + ((size_t)(b * HH + h) * TT + t) * DD) : vn;
        float2 vv = ((const float2*)vr)[lane];
        float p = sc[i];
        acc.x = fmaf(p, vv.x, acc.x);
        acc.y = fmaf(p, vv.y, acc.y);
    }
    cp[w][2 * lane] = acc.x;
    cp[w][2 * lane + 1] = acc.y;
    __syncthreads();
    if (tid < DD) {
        float s = 0.f;
        #pragma unroll
        for (int ww = 0; ww < 8; ww++) s += cp[ww][tid];
        float* ap = &g_ap[((size_t)bh * TS + ts) * 66];
        if (tid == 0) { ap[0] = m; ap[1] = den; }
        ap[2 + tid] = s;
    }
}

// ---------------- residual (sum split partials + bias) + layernorm -> g_x ----------------
template<int SRC, int NS>
__global__ void resid_ln_kernel(const float* __restrict__ bias,
                                const float* __restrict__ lw,
                                const float* __restrict__ lb) {
    __shared__ float s[EE];
    __shared__ float red[8];
    const float* part = scratch_buf<SRC>();
    int b = blockIdx.x, tid = threadIdx.x;
    for (int e = tid; e < EE; e += 256) {
        float v = g_h[b * EE + e] + bias[e];
        #pragma unroll 8
        for (int sp = 0; sp < NS; sp++)
            v += part[(size_t)(sp * 8 + b) * EE + e];
        s[e] = v;
        g_h[b * EE + e] = v;
    }
    __syncthreads();
    float ls = 0.f;
    for (int e = tid; e < EE; e += 256) ls += s[e];
    float mean = blockReduceSum(ls, red) * (1.f / EE);
    ls = 0.f;
    for (int e = tid; e < EE; e += 256) { float d = s[e] - mean; ls += d * d; }
    float rstd = rsqrtf(blockReduceSum(ls, red) * (1.f / EE) + 1e-5f);
    for (int e = tid; e < EE; e += 256)
        g_x[b * EE + e] = (s[e] - mean) * rstd * lw[e] + lb[e];
}

// ---------------- logits: warp per vocab row (x2), 8-batch reuse ----------------
__global__ void logits_kernel(const float* __restrict__ wte) {
    __shared__ __align__(16) float4 xs[8][256];
    int tid = threadIdx.x;
    for (int i = tid; i < 2048; i += 256) {
        int b = i >> 8, j = i & 255;
        xs[b][j] = ((const float4*)g_x)[b * 256 + j];
    }
    __syncthreads();
    int w = blockIdx.x * 8 + (tid >> 5);
    int lane = tid & 31;
    int nw = gridDim.x * 8;
    for (int v0 = w * 2; v0 < VV; v0 += nw * 2) {
        int v1 = v0 + 1;
        bool has1 = (v1 < VV);
        const float4* r0 = (const float4*)(wte + (size_t)v0 * EE);
        const float4* r1 = (const float4*)(wte + (size_t)(has1 ? v1 : v0) * EE);
        float a0[8], a1[8];
        #pragma unroll
        for (int b = 0; b < 8; b++) { a0[b] = 0.f; a1[b] = 0.f; }
        #pragma unroll
        for (int i = 0; i < 8; i++) {
            int idx = lane + 32 * i;
            float4 w0 = r0[idx];
            float4 w1 = r1[idx];
            #pragma unroll
            for (int b = 0; b < 8; b++) {
                float4 xb = xs[b][idx];
                a0[b] += w0.x * xb.x + w0.y * xb.y + w0.z * xb.z + w0.w * xb.w;
                a1[b] += w1.x * xb.x + w1.y * xb.y + w1.z * xb.z + w1.w * xb.w;
            }
        }
        #pragma unroll
        for (int b = 0; b < 8; b++) {
            #pragma unroll
            for (int o = 16; o; o >>= 1) {
                a0[b] += __shfl_down_sync(0xffffffffu, a0[b], o);
                a1[b] += __shfl_down_sync(0xffffffffu, a1[b], o);
            }
        }
        if (lane == 0) {
            #pragma unroll
            for (int b = 0; b < 8; b++) {
                g_logits[(size_t)b * VV + v0] = a0[b];
                if (has1) g_logits[(size_t)b * VV + v1] = a1[b];
            }
        }
    }
}

__global__ void softmax_stats_kernel() {
    __shared__ float red[8];
    int b = blockIdx.x, tid = threadIdx.x;
    float m = -1e30f;
    for (int v = tid; v < VV; v += 256) m = fmaxf(m, g_logits[(size_t)b * VV + v]);
    m = blockReduceMax(m, red);
    float s = 0.f;
    for (int v = tid; v < VV; v += 256) s += __expf(g_logits[(size_t)b * VV + v] - m);
    s = blockReduceSum(s, red);
    if (tid == 0) { g_stats[b * 2] = m; g_stats[b * 2 + 1] = s; }
}

__global__ void softmax_norm_kernel(float* __restrict__ out) {
    int i = blockIdx.x * 256 + threadIdx.x;
    if (i < BB * VV) {
        int b = i / VV;
        out[i] = __expf(g_logits[i] - g_stats[b * 2]) * (1.f / g_stats[b * 2 + 1]);
    }
}

// ---------------- launch ----------------
extern "C" void kernel_launch(void* const* d_in, const int* in_sizes, int n_in,
                              void* d_out, int out_size) {
    const int*   ids  = (const int*)  d_in[0];
    const float* kc   = (const float*)d_in[1];
    const float* vc   = (const float*)d_in[2];
    const float* wte  = (const float*)d_in[3];
    const float* wpe  = (const float*)d_in[4];
    const float* l1w  = (const float*)d_in[5];
    const float* l1b  = (const float*)d_in[6];
    const float* caw  = (const float*)d_in[7];
    const float* cab  = (const float*)d_in[8];
    const float* apw  = (const float*)d_in[9];
    const float* apb  = (const float*)d_in[10];
    const float* l2w  = (const float*)d_in[11];
    const float* l2b  = (const float*)d_in[12];
    const float* fw   = (const float*)d_in[13];
    const float* fb   = (const float*)d_in[14];
    const float* pw   = (const float*)d_in[15];
    const float* pb   = (const float*)d_in[16];
    const float* lnfw = (const float*)d_in[17];
    const float* lnfb = (const float*)d_in[18];
    const float* ab   = (const float*)d_in[19];
    float* out = (float*)d_out;

    embed_kernel<<<BB, 256>>>(ids, wte, wpe, l1w, l1b);

    for (int l = 0; l < LL; l++) {
        // qkv = x @ c_attn_w   (N=3072, K=1024, 32 K-splits)  -> 192 blocks
        gemv_k<32, 3 * EE, EE, BUF_QKV><<<dim3(6, QS), 256>>>(caw + (size_t)l * EE * 3 * EE);

        // flash-decode attention over 1023 cached + 1 new key  -> 512 blocks
        attn_kernel<<<dim3(BB * HH, TS), 256>>>(
            kc + (size_t)l * BB * HH * TT * DD,
            vc + (size_t)l * BB * HH * TT * DD,
            cab + (size_t)l * 3 * EE,
            ab + l);

        // attn proj (combine fused into input stage)  -> 64 blocks
        gemv_ctx_k<32, EE, BUF_APROJ><<<dim3(2, AS), 256>>>(apw + (size_t)l * EE * EE);

        // h += attnout + apb ; x = ln2(h)
        resid_ln_kernel<BUF_APROJ, AS><<<BB, 256>>>(apb + (size_t)l * EE,
                                                    l2w + (size_t)l * EE,
                                                    l2b + (size_t)l * EE);

        // fc = x @ fc_w  (N=4096, K=1024) -> 256 blocks
        gemv_k<32, FF, EE, BUF_FC><<<dim3(8, FS), 256>>>(fw + (size_t)l * EE * FF);

        // mlp proj = gelu(fc + fb) @ pw  (N=1024, K=4096) -> 128 blocks
        gemv_gelu_k<64, EE, BUF_MP><<<dim3(2, MS), 256>>>(fb + (size_t)l * FF,
                                                          pw + (size_t)l * FF * EE);

        // h += mlpout + pb ; x = ln1(h,l+1)  (or lnf at the last layer)
        const float* nlw = (l < LL - 1) ? (l1w + (size_t)(l + 1) * EE) : lnfw;
        const float* nlb = (l < LL - 1) ? (l1b + (size_t)(l + 1) * EE) : lnfb;
        resid_ln_kernel<BUF_MP, MS><<<BB, 256>>>(pb + (size_t)l * EE, nlw, nlb);
    }

    logits_kernel<<<1184, 256>>>(wte);
    softmax_stats_kernel<<<BB, 256>>>();
    softmax_norm_kernel<<<(BB * VV + 255) / 256, 256>>>(out);
}

// round 8
// speedup vs baseline: 1.2836x; 1.2836x over previous
#include <cuda_runtime.h>
#include <cuda_bf16.h>
#include <math.h>

// Problem constants
#define LL 12
#define BB 8
#define HH 16
#define DD 64
#define EE 1024
#define FF 4096
#define VV 50257
#define TT 1023
#define SS 1024

// Split configs
#define QS 64    // qkv K-splits (K=1024/16)
#define FS 32    // fc K-splits (K=1024/32)
#define AS 64    // attnproj K-splits (K=1024/16)
#define MS 128   // mlpproj K-splits (K=4096/32)
#define TS 8     // attention T splits (1024/128)

// ---------------- scratch (static device, no allocation) ----------------
__device__ __align__(16) float g_h[BB * EE];
__device__ __align__(16) float g_x[BB * EE];
__device__ __align__(16) float g_qkv[QS * BB * 3 * EE];
__device__ __align__(16) float g_qkvc[BB * 3 * EE];       // combined qkv
__device__ __align__(16) float g_ap[BB * HH * TS * 66];   // [bh][ts][m,den,64 vals]
__device__ __align__(16) float g_aproj[AS * BB * EE];
__device__ __align__(16) float g_fc[FS * BB * FF];
__device__ __align__(16) float g_mp[MS * BB * EE];
__device__ __align__(16) float g_logits[BB * VV];
__device__ __align__(16) float g_stats[BB * 2];

// Scratch selection happens in DEVICE code only — passing __device__ symbols
// as kernel arguments from host code yields a bogus address.
#define BUF_QKV   0
#define BUF_APROJ 1
#define BUF_FC    2
#define BUF_MP    3
template<int ID>
__device__ __forceinline__ float* scratch_buf() {
    if (ID == BUF_QKV)   return g_qkv;
    if (ID == BUF_APROJ) return g_aproj;
    if (ID == BUF_FC)    return g_fc;
    return g_mp;
}

// ---------------- reductions (256 threads) ----------------
__device__ __forceinline__ float blockReduceSum(float v, float* red) {
    #pragma unroll
    for (int o = 16; o; o >>= 1) v += __shfl_down_sync(0xffffffffu, v, o);
    int tid = threadIdx.x;
    if ((tid & 31) == 0) red[tid >> 5] = v;
    __syncthreads();
    if (tid == 0) {
        float s = red[0];
        #pragma unroll
        for (int i = 1; i < 8; i++) s += red[i];
        red[0] = s;
    }
    __syncthreads();
    float r = red[0];
    __syncthreads();
    return r;
}

__device__ __forceinline__ float blockReduceMax(float v, float* red) {
    #pragma unroll
    for (int o = 16; o; o >>= 1) v = fmaxf(v, __shfl_down_sync(0xffffffffu, v, o));
    int tid = threadIdx.x;
    if ((tid & 31) == 0) red[tid >> 5] = v;
    __syncthreads();
    if (tid == 0) {
        float s = red[0];
        #pragma unroll
        for (int i = 1; i < 8; i++) s = fmaxf(s, red[i]);
        red[0] = s;
    }
    __syncthreads();
    float r = red[0];
    __syncthreads();
    return r;
}

// ---------------- embed + ln1(layer 0) ----------------
__global__ void embed_kernel(const int* __restrict__ ids,
                             const float* __restrict__ wte,
                             const float* __restrict__ wpe,
                             const float* __restrict__ lw,
                             const float* __restrict__ lb) {
    __shared__ float red[8];
    int b = blockIdx.x, tid = threadIdx.x;   // 256 threads, one float4 each
    int id = ids[b * SS + (SS - 1)];
    float4 v = ((const float4*)(wte + (size_t)id * EE))[tid];
    float4 p = ((const float4*)(wpe + (size_t)(SS - 1) * EE))[tid];
    v.x += p.x; v.y += p.y; v.z += p.z; v.w += p.w;
    ((float4*)g_h)[b * 256 + tid] = v;
    float ls = v.x + v.y + v.z + v.w;
    float mean = blockReduceSum(ls, red) * (1.f / EE);
    float dx = v.x - mean, dy = v.y - mean, dz = v.z - mean, dw = v.w - mean;
    ls = dx * dx + dy * dy + dz * dz + dw * dw;
    float rstd = rsqrtf(blockReduceSum(ls, red) * (1.f / EE) + 1e-5f);
    float4 w4 = ((const float4*)lw)[tid];
    float4 b4 = ((const float4*)lb)[tid];
    float4 o;
    o.x = dx * rstd * w4.x + b4.x;
    o.y = dy * rstd * w4.y + b4.y;
    o.z = dz * rstd * w4.z + b4.z;
    o.w = dw * rstd * w4.w + b4.w;
    ((float4*)g_x)[b * 256 + tid] = o;
}

// ---------------- GEMV core: 8-batch split-K partial, float2 columns ----------------
template<int KC, int N>
__device__ __forceinline__ void gemv_core(const float* xs,
                                          const float* __restrict__ W,
                                          float* __restrict__ part) {
    int tid = threadIdx.x;
    int k0 = blockIdx.y * KC;
    int n2 = blockIdx.x * 256 + tid;                // float2 column index
    const float2* wp = ((const float2*)W) + (size_t)k0 * (N / 2) + n2;
    float2 acc[8];
    #pragma unroll
    for (int b = 0; b < 8; b++) { acc[b].x = 0.f; acc[b].y = 0.f; }
    #pragma unroll
    for (int k = 0; k < KC; k++) {
        float2 wv = wp[(size_t)k * (N / 2)];
        #pragma unroll
        for (int b = 0; b < 8; b++) {
            float xv = xs[b * KC + k];
            acc[b].x = fmaf(xv, wv.x, acc[b].x);
            acc[b].y = fmaf(xv, wv.y, acc[b].y);
        }
    }
    float2* p2 = (float2*)part;
    int sp = blockIdx.y;
    #pragma unroll
    for (int b = 0; b < 8; b++)
        p2[(size_t)(sp * 8 + b) * (N / 2) + n2] = acc[b];
}

// plain: input = g_x, output = scratch_buf<DST>
template<int KC, int N, int K, int DST>
__global__ void __launch_bounds__(256) gemv_k(const float* __restrict__ W) {
    __shared__ float xs[8 * KC];
    int tid = threadIdx.x;
    int k0 = blockIdx.y * KC;
    for (int i = tid; i < 8 * KC; i += 256) {
        int b = i / KC, k = i % KC;
        xs[i] = g_x[b * K + k0 + k];
    }
    __syncthreads();
    gemv_core<KC, N>(xs, W, scratch_buf<DST>());
}

// gelu: input = sum of fc partials + bias, gelu'd  (K = FF)
template<int KC, int N, int DST>
__global__ void __launch_bounds__(256) gemv_gelu_k(const float* __restrict__ fcb,
                                                   const float* __restrict__ W) {
    __shared__ float xs[8 * KC];
    int tid = threadIdx.x;
    int k0 = blockIdx.y * KC;
    for (int i = tid; i < 8 * KC; i += 256) {
        int b = i / KC, k = k0 + i % KC;
        float v = fcb[k];
        #pragma unroll
        for (int s = 0; s < FS; s++) v += g_fc[(size_t)(s * 8 + b) * FF + k];
        float c3 = v * v * v;
        xs[i] = 0.5f * v * (1.f + tanhf(0.7978845608028654f * (v + 0.044715f * c3)));
    }
    __syncthreads();
    gemv_core<KC, N>(xs, W, scratch_buf<DST>());
}

// ctx: input built from attention partials (flash-decode combine), K = EE
template<int KC, int N, int DST>
__global__ void __launch_bounds__(256) gemv_ctx_k(const float* __restrict__ W) {
    __shared__ float xs[8 * KC];   // KC=16 -> 128 entries
    int tid = threadIdx.x;
    int k0 = blockIdx.y * KC;
    if (tid < 8 * KC) {
        int b = tid / KC;
        int kg = k0 + tid % KC;
        int head = kg >> 6, d = kg & 63;
        int bh = b * HH + head;
        const float* ap = &g_ap[(size_t)bh * TS * 66];
        float gm = -1e30f;
        #pragma unroll
        for (int ts = 0; ts < TS; ts++) gm = fmaxf(gm, ap[ts * 66]);
        float den = 0.f, val = 0.f;
        #pragma unroll
        for (int ts = 0; ts < TS; ts++) {
            float e = __expf(ap[ts * 66] - gm);
            den += ap[ts * 66 + 1] * e;
            val += ap[ts * 66 + 2 + d] * e;
        }
        xs[tid] = val / den;
    }
    __syncthreads();
    gemv_core<KC, N>(xs, W, scratch_buf<DST>());
}

// ---------------- qkv combine: sum splits + bias -> g_qkvc ----------------
__global__ void qkvc_kernel(const float* __restrict__ cab) {
    int j4 = blockIdx.x * 256 + threadIdx.x;   // 0..6143 float4 (8 x 768)
    int b = j4 / 768, c4 = j4 - b * 768;
    float4 v = ((const float4*)cab)[c4];
    #pragma unroll 16
    for (int sp = 0; sp < QS; sp++) {
        float4 p = ((const float4*)g_qkv)[(size_t)(sp * 8 + b) * 768 + c4];
        v.x += p.x; v.y += p.y; v.z += p.z; v.w += p.w;
    }
    ((float4*)g_qkvc)[j4] = v;
}

// ---------------- attention (flash-decode, split over T, float4 rows) ----------------
__global__ void __launch_bounds__(256) attn_kernel(const float* __restrict__ kc,
                                                   const float* __restrict__ vc,
                                                   const float* __restrict__ abp) {
    __shared__ float sc[128];
    __shared__ float red[8];
    __shared__ __align__(16) float cp[16][64];
    int tid = threadIdx.x;
    int bh = blockIdx.x;
    int b = bh >> 4, h = bh & 15;
    int ts = blockIdx.y;
    int w = tid >> 5, lane = tid & 31;
    int half = lane >> 4, sub = lane & 15;

    const float* qrow = g_qkvc + b * 3 * EE + h * DD;
    float4 qv = ((const float4*)qrow)[sub];
    const float* knp = qrow + EE;          // new key row
    const float* vnp = qrow + 2 * EE;      // new value row
    size_t rowbase = (size_t)(b * HH + h) * TT;
    int t0 = ts * 128;
    float abias = abp[0];

    // scores: each warp does 2 keys per iter (16 lanes x float4 per key)
    #pragma unroll
    for (int it = 0; it < 8; it++) {
        int i = it * 16 + w * 2 + half;
        int t = t0 + i;
        const float4* kr = (const float4*)((t < TT) ? (kc + (rowbase + t) * DD) : knp);
        float4 kk = kr[sub];
        float p = kk.x * qv.x + kk.y * qv.y + kk.z * qv.z + kk.w * qv.w;
        p += __shfl_xor_sync(0xffffffffu, p, 8);
        p += __shfl_xor_sync(0xffffffffu, p, 4);
        p += __shfl_xor_sync(0xffffffffu, p, 2);
        p += __shfl_xor_sync(0xffffffffu, p, 1);
        if (sub == 0) sc[i] = p * 0.125f + abias;
    }
    __syncthreads();

    float m = blockReduceMax((tid < 128) ? sc[tid] : -1e30f, red);
    float e = (tid < 128) ? __expf(sc[tid] - m) : 0.f;
    if (tid < 128) sc[tid] = e;
    float den = blockReduceSum(e, red);   // internal syncs publish sc[]

    float4 acc; acc.x = acc.y = acc.z = acc.w = 0.f;
    #pragma unroll
    for (int it = 0; it < 8; it++) {
        int i = it * 16 + w * 2 + half;
        int t = t0 + i;
        const float4* vr = (const float4*)((t < TT) ? (vc + (rowbase + t) * DD) : vnp);
        float4 vv = vr[sub];
        float p = sc[i];
        acc.x = fmaf(p, vv.x, acc.x);
        acc.y = fmaf(p, vv.y, acc.y);
        acc.z = fmaf(p, vv.z, acc.z);
        acc.w = fmaf(p, vv.w, acc.w);
    }
    ((float4*)cp[w * 2 + half])[sub] = acc;
    __syncthreads();
    if (tid < DD) {
        float s = 0.f;
        #pragma unroll
        for (int g = 0; g < 16; g++) s += cp[g][tid];
        float* ap = &g_ap[((size_t)bh * TS + ts) * 66];
        if (tid == 0) { ap[0] = m; ap[1] = den; }
        ap[2 + tid] = s;
    }
}

// ---------------- residual (sum split partials + bias) + layernorm -> g_x ----------------
template<int SRC, int NS>
__global__ void __launch_bounds__(256) resid_ln_kernel(const float* __restrict__ bias,
                                                       const float* __restrict__ lw,
                                                       const float* __restrict__ lb) {
    __shared__ float red[8];
    const float4* part = (const float4*)scratch_buf<SRC>();
    int b = blockIdx.x, tid = threadIdx.x;   // 256 threads, one float4 each
    float4 v = ((const float4*)g_h)[b * 256 + tid];
    float4 bv = ((const float4*)bias)[tid];
    v.x += bv.x; v.y += bv.y; v.z += bv.z; v.w += bv.w;
    #pragma unroll 16
    for (int sp = 0; sp < NS; sp++) {
        float4 p = part[(size_t)(sp * 8 + b) * 256 + tid];
        v.x += p.x; v.y += p.y; v.z += p.z; v.w += p.w;
    }
    ((float4*)g_h)[b * 256 + tid] = v;
    float ls = v.x + v.y + v.z + v.w;
    float mean = blockReduceSum(ls, red) * (1.f / EE);
    float dx = v.x - mean, dy = v.y - mean, dz = v.z - mean, dw = v.w - mean;
    ls = dx * dx + dy * dy + dz * dz + dw * dw;
    float rstd = rsqrtf(blockReduceSum(ls, red) * (1.f / EE) + 1e-5f);
    float4 w4 = ((const float4*)lw)[tid];
    float4 b4 = ((const float4*)lb)[tid];
    float4 o;
    o.x = dx * rstd * w4.x + b4.x;
    o.y = dy * rstd * w4.y + b4.y;
    o.z = dz * rstd * w4.z + b4.z;
    o.w = dw * rstd * w4.w + b4.w;
    ((float4*)g_x)[b * 256 + tid] = o;
}

// ---------------- logits: warp per vocab row (x2), 8-batch reuse ----------------
__global__ void __launch_bounds__(256) logits_kernel(const float* __restrict__ wte) {
    __shared__ __align__(16) float4 xs[8][256];
    int tid = threadIdx.x;
    for (int i = tid; i < 2048; i += 256) {
        int b = i >> 8, j = i & 255;
        xs[b][j] = ((const float4*)g_x)[b * 256 + j];
    }
    __syncthreads();
    int w = blockIdx.x * 8 + (tid >> 5);
    int lane = tid & 31;
    int nw = gridDim.x * 8;
    for (int v0 = w * 2; v0 < VV; v0 += nw * 2) {
        int v1 = v0 + 1;
        bool has1 = (v1 < VV);
        const float4* r0 = (const float4*)(wte + (size_t)v0 * EE);
        const float4* r1 = (const float4*)(wte + (size_t)(has1 ? v1 : v0) * EE);
        float a0[8], a1[8];
        #pragma unroll
        for (int b = 0; b < 8; b++) { a0[b] = 0.f; a1[b] = 0.f; }
        #pragma unroll
        for (int i = 0; i < 8; i++) {
            int idx = lane + 32 * i;
            float4 w0 = r0[idx];
            float4 w1 = r1[idx];
            #pragma unroll
            for (int b = 0; b < 8; b++) {
                float4 xb = xs[b][idx];
                a0[b] += w0.x * xb.x + w0.y * xb.y + w0.z * xb.z + w0.w * xb.w;
                a1[b] += w1.x * xb.x + w1.y * xb.y + w1.z * xb.z + w1.w * xb.w;
            }
        }
        #pragma unroll
        for (int b = 0; b < 8; b++) {
            #pragma unroll
            for (int o = 16; o; o >>= 1) {
                a0[b] += __shfl_down_sync(0xffffffffu, a0[b], o);
                a1[b] += __shfl_down_sync(0xffffffffu, a1[b], o);
            }
        }
        if (lane == 0) {
            #pragma unroll
            for (int b = 0; b < 8; b++) {
                g_logits[(size_t)b * VV + v0] = a0[b];
                if (has1) g_logits[(size_t)b * VV + v1] = a1[b];
            }
        }
    }
}

__global__ void softmax_stats_kernel() {
    __shared__ float red[8];
    int b = blockIdx.x, tid = threadIdx.x;
    float m = -1e30f;
    for (int v = tid; v < VV; v += 256) m = fmaxf(m, g_logits[(size_t)b * VV + v]);
    m = blockReduceMax(m, red);
    float s = 0.f;
    for (int v = tid; v < VV; v += 256) s += __expf(g_logits[(size_t)b * VV + v] - m);
    s = blockReduceSum(s, red);
    if (tid == 0) { g_stats[b * 2] = m; g_stats[b * 2 + 1] = s; }
}

__global__ void softmax_norm_kernel(float* __restrict__ out) {
    int i = blockIdx.x * 256 + threadIdx.x;
    if (i < BB * VV) {
        int b = i / VV;
        out[i] = __expf(g_logits[i] - g_stats[b * 2]) * (1.f / g_stats[b * 2 + 1]);
    }
}

// ---------------- launch ----------------
extern "C" void kernel_launch(void* const* d_in, const int* in_sizes, int n_in,
                              void* d_out, int out_size) {
    const int*   ids  = (const int*)  d_in[0];
    const float* kc   = (const float*)d_in[1];
    const float* vc   = (const float*)d_in[2];
    const float* wte  = (const float*)d_in[3];
    const float* wpe  = (const float*)d_in[4];
    const float* l1w  = (const float*)d_in[5];
    const float* l1b  = (const float*)d_in[6];
    const float* caw  = (const float*)d_in[7];
    const float* cab  = (const float*)d_in[8];
    const float* apw  = (const float*)d_in[9];
    const float* apb  = (const float*)d_in[10];
    const float* l2w  = (const float*)d_in[11];
    const float* l2b  = (const float*)d_in[12];
    const float* fw   = (const float*)d_in[13];
    const float* fb   = (const float*)d_in[14];
    const float* pw   = (const float*)d_in[15];
    const float* pb   = (const float*)d_in[16];
    const float* lnfw = (const float*)d_in[17];
    const float* lnfb = (const float*)d_in[18];
    const float* ab   = (const float*)d_in[19];
    float* out = (float*)d_out;

    embed_kernel<<<BB, 256>>>(ids, wte, wpe, l1w, l1b);

    for (int l = 0; l < LL; l++) {
        // qkv = x @ c_attn_w  (N=3072, K=1024, 64 K-splits) -> 384 blocks
        gemv_k<16, 3 * EE, EE, BUF_QKV><<<dim3(6, QS), 256>>>(caw + (size_t)l * EE * 3 * EE);

        // combine qkv splits + bias -> g_qkvc (24 blocks)
        qkvc_kernel<<<24, 256>>>(cab + (size_t)l * 3 * EE);

        // flash-decode attention: 1024 blocks, float4 rows
        attn_kernel<<<dim3(BB * HH, TS), 256>>>(
            kc + (size_t)l * BB * HH * TT * DD,
            vc + (size_t)l * BB * HH * TT * DD,
            ab + l);

        // attn proj (combine fused into input stage) -> 128 blocks
        gemv_ctx_k<16, EE, BUF_APROJ><<<dim3(2, AS), 256>>>(apw + (size_t)l * EE * EE);

        // h += attnout + apb ; x = ln2(h)
        resid_ln_kernel<BUF_APROJ, AS><<<BB, 256>>>(apb + (size_t)l * EE,
                                                    l2w + (size_t)l * EE,
                                                    l2b + (size_t)l * EE);

        // fc = x @ fc_w  (N=4096, K=1024) -> 256 blocks
        gemv_k<32, FF, EE, BUF_FC><<<dim3(8, FS), 256>>>(fw + (size_t)l * EE * FF);

        // mlp proj = gelu(fc + fb) @ pw  (N=1024, K=4096, 128 splits) -> 256 blocks
        gemv_gelu_k<32, EE, BUF_MP><<<dim3(2, MS), 256>>>(fb + (size_t)l * FF,
                                                          pw + (size_t)l * FF * EE);

        // h += mlpout + pb ; x = ln1(h,l+1)  (or lnf at the last layer)
        const float* nlw = (l < LL - 1) ? (l1w + (size_t)(l + 1) * EE) : lnfw;
        const float* nlb = (l < LL - 1) ? (l1b + (size_t)(l + 1) * EE) : lnfb;
        resid_ln_kernel<BUF_MP, MS><<<BB, 256>>>(pb + (size_t)l * EE, nlw, nlb);
    }

    logits_kernel<<<1184, 256>>>(wte);
    softmax_stats_kernel<<<BB, 256>>>();
    softmax_norm_kernel<<<(BB * VV + 255) / 256, 256>>>(out);
}

// round 9
// speedup vs baseline: 1.2971x; 1.0105x over previous
#include <cuda_runtime.h>
#include <cuda_bf16.h>
#include <math.h>

// Problem constants
#define LL 12
#define BB 8
#define HH 16
#define DD 64
#define EE 1024
#define FF 4096
#define VV 50257
#define TT 1023
#define SS 1024

// Split configs
#define QS 32    // qkv K-splits (K=1024/32)
#define FS 32    // fc K-splits (K=1024/32)
#define AS 32    // attnproj K-splits (K=1024/32)
#define MS 64    // mlpproj K-splits (K=4096/64)
#define TS 8     // attention T splits (1024/128)

// ---------------- scratch (static device, no allocation) ----------------
__device__ __align__(16) float g_h[BB * EE];
__device__ __align__(16) float g_x[BB * EE];
__device__ __align__(16) float g_qkv[QS * BB * 3 * EE];
__device__ __align__(16) float g_ap[BB * HH * TS * 66];   // [bh][ts][m,den,64 vals]
__device__ __align__(16) float g_aproj[AS * BB * EE];
__device__ __align__(16) float g_fc[FS * BB * FF];
__device__ __align__(16) float g_mp[MS * BB * EE];
__device__ __align__(16) float g_logits[BB * VV];
__device__ __align__(16) float g_stats[BB * 2];

// Scratch selection happens in DEVICE code only — passing __device__ symbols
// as kernel arguments from host code yields a bogus address.
#define BUF_QKV   0
#define BUF_APROJ 1
#define BUF_FC    2
#define BUF_MP    3
template<int ID>
__device__ __forceinline__ float* scratch_buf() {
    if (ID == BUF_QKV)   return g_qkv;
    if (ID == BUF_APROJ) return g_aproj;
    if (ID == BUF_FC)    return g_fc;
    return g_mp;
}

// ---------------- reductions (256 threads) ----------------
__device__ __forceinline__ float blockReduceSum(float v, float* red) {
    #pragma unroll
    for (int o = 16; o; o >>= 1) v += __shfl_down_sync(0xffffffffu, v, o);
    int tid = threadIdx.x;
    if ((tid & 31) == 0) red[tid >> 5] = v;
    __syncthreads();
    if (tid == 0) {
        float s = red[0];
        #pragma unroll
        for (int i = 1; i < 8; i++) s += red[i];
        red[0] = s;
    }
    __syncthreads();
    float r = red[0];
    __syncthreads();
    return r;
}

__device__ __forceinline__ float blockReduceMax(float v, float* red) {
    #pragma unroll
    for (int o = 16; o; o >>= 1) v = fmaxf(v, __shfl_down_sync(0xffffffffu, v, o));
    int tid = threadIdx.x;
    if ((tid & 31) == 0) red[tid >> 5] = v;
    __syncthreads();
    if (tid == 0) {
        float s = red[0];
        #pragma unroll
        for (int i = 1; i < 8; i++) s = fmaxf(s, red[i]);
        red[0] = s;
    }
    __syncthreads();
    float r = red[0];
    __syncthreads();
    return r;
}

// ---------------- embed + ln1(layer 0) ----------------
__global__ void embed_kernel(const int* __restrict__ ids,
                             const float* __restrict__ wte,
                             const float* __restrict__ wpe,
                             const float* __restrict__ lw,
                             const float* __restrict__ lb) {
    __shared__ float red[8];
    int b = blockIdx.x, tid = threadIdx.x;   // 256 threads, one float4 each
    int id = ids[b * SS + (SS - 1)];
    float4 v = ((const float4*)(wte + (size_t)id * EE))[tid];
    float4 p = ((const float4*)(wpe + (size_t)(SS - 1) * EE))[tid];
    v.x += p.x; v.y += p.y; v.z += p.z; v.w += p.w;
    ((float4*)g_h)[b * 256 + tid] = v;
    float ls = v.x + v.y + v.z + v.w;
    float mean = blockReduceSum(ls, red) * (1.f / EE);
    float dx = v.x - mean, dy = v.y - mean, dz = v.z - mean, dw = v.w - mean;
    ls = dx * dx + dy * dy + dz * dz + dw * dw;
    float rstd = rsqrtf(blockReduceSum(ls, red) * (1.f / EE) + 1e-5f);
    float4 w4 = ((const float4*)lw)[tid];
    float4 b4 = ((const float4*)lb)[tid];
    float4 o;
    o.x = dx * rstd * w4.x + b4.x;
    o.y = dy * rstd * w4.y + b4.y;
    o.z = dz * rstd * w4.z + b4.z;
    o.w = dw * rstd * w4.w + b4.w;
    ((float4*)g_x)[b * 256 + tid] = o;
}

// ---------------- GEMV core: 8-batch split-K partial, float2 columns ----------------
template<int KC, int N>
__device__ __forceinline__ void gemv_core(const float* xs,
                                          const float* __restrict__ W,
                                          float* __restrict__ part) {
    int tid = threadIdx.x;
    int k0 = blockIdx.y * KC;
    int n2 = blockIdx.x * 256 + tid;                // float2 column index
    const float2* wp = ((const float2*)W) + (size_t)k0 * (N / 2) + n2;
    float2 acc[8];
    #pragma unroll
    for (int b = 0; b < 8; b++) { acc[b].x = 0.f; acc[b].y = 0.f; }
    #pragma unroll 16
    for (int k = 0; k < KC; k++) {
        float2 wv = wp[(size_t)k * (N / 2)];
        #pragma unroll
        for (int b = 0; b < 8; b++) {
            float xv = xs[b * KC + k];
            acc[b].x = fmaf(xv, wv.x, acc[b].x);
            acc[b].y = fmaf(xv, wv.y, acc[b].y);
        }
    }
    float2* p2 = (float2*)part;
    int sp = blockIdx.y;
    #pragma unroll
    for (int b = 0; b < 8; b++)
        p2[(size_t)(sp * 8 + b) * (N / 2) + n2] = acc[b];
}

// plain: input = g_x, output = scratch_buf<DST>
template<int KC, int N, int K, int DST>
__global__ void __launch_bounds__(256) gemv_k(const float* __restrict__ W) {
    __shared__ float xs[8 * KC];
    int tid = threadIdx.x;
    int k0 = blockIdx.y * KC;
    for (int i = tid; i < 8 * KC; i += 256) {
        int b = i / KC, k = i % KC;
        xs[i] = g_x[b * K + k0 + k];
    }
    __syncthreads();
    gemv_core<KC, N>(xs, W, scratch_buf<DST>());
}

// gelu: input = sum of fc partials + bias, gelu'd  (K = FF)
template<int KC, int N, int DST>
__global__ void __launch_bounds__(256) gemv_gelu_k(const float* __restrict__ fcb,
                                                   const float* __restrict__ W) {
    __shared__ float xs[8 * KC];
    int tid = threadIdx.x;
    int k0 = blockIdx.y * KC;
    for (int i = tid; i < 8 * KC; i += 256) {
        int b = i / KC, k = k0 + i % KC;
        float v = fcb[k];
        #pragma unroll 16
        for (int s = 0; s < FS; s++) v += g_fc[(size_t)(s * 8 + b) * FF + k];
        float c3 = v * v * v;
        xs[i] = 0.5f * v * (1.f + tanhf(0.7978845608028654f * (v + 0.044715f * c3)));
    }
    __syncthreads();
    gemv_core<KC, N>(xs, W, scratch_buf<DST>());
}

// ctx: input built from attention partials (flash-decode combine), K = EE
template<int KC, int N, int DST>
__global__ void __launch_bounds__(256) gemv_ctx_k(const float* __restrict__ W) {
    __shared__ float xs[8 * KC];
    int tid = threadIdx.x;
    int k0 = blockIdx.y * KC;
    if (tid < 8 * KC) {
        int b = tid / KC;
        int kg = k0 + tid % KC;
        int head = kg >> 6, d = kg & 63;
        int bh = b * HH + head;
        const float* ap = &g_ap[(size_t)bh * TS * 66];
        float gm = -1e30f;
        #pragma unroll
        for (int ts = 0; ts < TS; ts++) gm = fmaxf(gm, ap[ts * 66]);
        float den = 0.f, val = 0.f;
        #pragma unroll
        for (int ts = 0; ts < TS; ts++) {
            float e = __expf(ap[ts * 66] - gm);
            den += ap[ts * 66 + 1] * e;
            val += ap[ts * 66 + 2 + d] * e;
        }
        xs[tid] = val / den;
    }
    __syncthreads();
    gemv_core<KC, N>(xs, W, scratch_buf<DST>());
}

// ---------------- attention: one-pass online softmax, fused qkv combine ----------------
__global__ void __launch_bounds__(256) attn_kernel(const float* __restrict__ kc,
                                                   const float* __restrict__ vc,
                                                   const float* __restrict__ cab,
                                                   const float* __restrict__ abp) {
    __shared__ __align__(16) float qs[DD], kn[DD], vn[DD];
    __shared__ float gm_s[16], gd_s[16];
    __shared__ __align__(16) float gacc[16][DD];
    int tid = threadIdx.x;
    int bh = blockIdx.x;
    int b = bh >> 4, h = bh & 15;
    int ts = blockIdx.y;

    // fused qkv split-combine for this (b, head): 192 values (q,k_new,v_new)
    if (tid < 192) {
        int grp = tid >> 6;         // 0:q 1:k 2:v
        int d = tid & 63;
        int j = grp * EE + h * DD + d;
        float v = cab[j];
        #pragma unroll 16
        for (int s = 0; s < QS; s++) v += g_qkv[(size_t)(s * 8 + b) * (3 * EE) + j];
        if (grp == 0) qs[d] = v; else if (grp == 1) kn[d] = v; else vn[d] = v;
    }
    __syncthreads();

    int w = tid >> 5, lane = tid & 31;
    int half = lane >> 4, sub = lane & 15;
    int g = w * 2 + half;                 // 16 lane-groups of 16
    float4 qv = ((const float4*)qs)[sub];
    size_t rowbase = (size_t)(b * HH + h) * TT;
    int t0 = ts * 128;
    float abias = abp[0];

    float m = -1e30f, den = 0.f;
    float4 acc; acc.x = acc.y = acc.z = acc.w = 0.f;

    #pragma unroll
    for (int it = 0; it < 8; it++) {
        int i = it * 16 + g;
        int t = t0 + i;
        bool cached = (t < TT);
        const float4* kr = (const float4*)(cached ? (kc + (rowbase + t) * DD) : kn);
        const float4* vr = (const float4*)(cached ? (vc + (rowbase + t) * DD) : vn);
        float4 kk = kr[sub];
        float4 vv = vr[sub];               // independent of score -> issued early
        float p = kk.x * qv.x + kk.y * qv.y + kk.z * qv.z + kk.w * qv.w;
        p += __shfl_xor_sync(0xffffffffu, p, 8);
        p += __shfl_xor_sync(0xffffffffu, p, 4);
        p += __shfl_xor_sync(0xffffffffu, p, 2);
        p += __shfl_xor_sync(0xffffffffu, p, 1);
        p = p * 0.125f + abias;
        float mn = fmaxf(m, p);
        float scale = __expf(m - mn);      // first iter: exp(-huge) = 0
        float e = __expf(p - mn);
        den = den * scale + e;
        acc.x = acc.x * scale + e * vv.x;
        acc.y = acc.y * scale + e * vv.y;
        acc.z = acc.z * scale + e * vv.z;
        acc.w = acc.w * scale + e * vv.w;
        m = mn;
    }

    if (sub == 0) { gm_s[g] = m; gd_s[g] = den; }
    ((float4*)gacc[g])[sub] = acc;
    __syncthreads();

    if (tid < DD) {
        float gm = -1e30f;
        #pragma unroll
        for (int g2 = 0; g2 < 16; g2++) gm = fmaxf(gm, gm_s[g2]);
        float dd = 0.f, val = 0.f;
        #pragma unroll
        for (int g2 = 0; g2 < 16; g2++) {
            float e = __expf(gm_s[g2] - gm);
            dd += gd_s[g2] * e;
            val += gacc[g2][tid] * e;
        }
        float* ap = &g_ap[((size_t)bh * TS + ts) * 66];
        if (tid == 0) { ap[0] = gm; ap[1] = dd; }
        ap[2 + tid] = val;
    }
}

// ---------------- residual (sum split partials + bias) + layernorm -> g_x ----------------
template<int SRC, int NS>
__global__ void __launch_bounds__(256) resid_ln_kernel(const float* __restrict__ bias,
                                                       const float* __restrict__ lw,
                                                       const float* __restrict__ lb) {
    __shared__ float red[8];
    const float4* part = (const float4*)scratch_buf<SRC>();
    int b = blockIdx.x, tid = threadIdx.x;   // 256 threads, one float4 each
    float4 v = ((const float4*)g_h)[b * 256 + tid];
    float4 bv = ((const float4*)bias)[tid];
    v.x += bv.x; v.y += bv.y; v.z += bv.z; v.w += bv.w;
    #pragma unroll 16
    for (int sp = 0; sp < NS; sp++) {
        float4 p = part[(size_t)(sp * 8 + b) * 256 + tid];
        v.x += p.x; v.y += p.y; v.z += p.z; v.w += p.w;
    }
    ((float4*)g_h)[b * 256 + tid] = v;
    float ls = v.x + v.y + v.z + v.w;
    float mean = blockReduceSum(ls, red) * (1.f / EE);
    float dx = v.x - mean, dy = v.y - mean, dz = v.z - mean, dw = v.w - mean;
    ls = dx * dx + dy * dy + dz * dz + dw * dw;
    float rstd = rsqrtf(blockReduceSum(ls, red) * (1.f / EE) + 1e-5f);
    float4 w4 = ((const float4*)lw)[tid];
    float4 b4 = ((const float4*)lb)[tid];
    float4 o;
    o.x = dx * rstd * w4.x + b4.x;
    o.y = dy * rstd * w4.y + b4.y;
    o.z = dz * rstd * w4.z + b4.z;
    o.w = dw * rstd * w4.w + b4.w;
    ((float4*)g_x)[b * 256 + tid] = o;
}

// ---------------- logits: warp per vocab row (x2), 8-batch reuse ----------------
__global__ void __launch_bounds__(256) logits_kernel(const float* __restrict__ wte) {
    __shared__ __align__(16) float4 xs[8][256];
    int tid = threadIdx.x;
    for (int i = tid; i < 2048; i += 256) {
        int b = i >> 8, j = i & 255;
        xs[b][j] = ((const float4*)g_x)[b * 256 + j];
    }
    __syncthreads();
    int w = blockIdx.x * 8 + (tid >> 5);
    int lane = tid & 31;
    int nw = gridDim.x * 8;
    for (int v0 = w * 2; v0 < VV; v0 += nw * 2) {
        int v1 = v0 + 1;
        bool has1 = (v1 < VV);
        const float4* r0 = (const float4*)(wte + (size_t)v0 * EE);
        const float4* r1 = (const float4*)(wte + (size_t)(has1 ? v1 : v0) * EE);
        float a0[8], a1[8];
        #pragma unroll
        for (int b = 0; b < 8; b++) { a0[b] = 0.f; a1[b] = 0.f; }
        #pragma unroll
        for (int i = 0; i < 8; i++) {
            int idx = lane + 32 * i;
            float4 w0 = r0[idx];
            float4 w1 = r1[idx];
            #pragma unroll
            for (int b = 0; b < 8; b++) {
                float4 xb = xs[b][idx];
                a0[b] += w0.x * xb.x + w0.y * xb.y + w0.z * xb.z + w0.w * xb.w;
                a1[b] += w1.x * xb.x + w1.y * xb.y + w1.z * xb.z + w1.w * xb.w;
            }
        }
        #pragma unroll
        for (int b = 0; b < 8; b++) {
            #pragma unroll
            for (int o = 16; o; o >>= 1) {
                a0[b] += __shfl_down_sync(0xffffffffu, a0[b], o);
                a1[b] += __shfl_down_sync(0xffffffffu, a1[b], o);
            }
        }
        if (lane == 0) {
            #pragma unroll
            for (int b = 0; b < 8; b++) {
                g_logits[(size_t)b * VV + v0] = a0[b];
                if (has1) g_logits[(size_t)b * VV + v1] = a1[b];
            }
        }
    }
}

__global__ void softmax_stats_kernel() {
    __shared__ float red[8];
    int b = blockIdx.x, tid = threadIdx.x;
    float m = -1e30f;
    for (int v = tid; v < VV; v += 256) m = fmaxf(m, g_logits[(size_t)b * VV + v]);
    m = blockReduceMax(m, red);
    float s = 0.f;
    for (int v = tid; v < VV; v += 256) s += __expf(g_logits[(size_t)b * VV + v] - m);
    s = blockReduceSum(s, red);
    if (tid == 0) { g_stats[b * 2] = m; g_stats[b * 2 + 1] = s; }
}

__global__ void softmax_norm_kernel(float* __restrict__ out) {
    int i = blockIdx.x * 256 + threadIdx.x;
    if (i < BB * VV) {
        int b = i / VV;
        out[i] = __expf(g_logits[i] - g_stats[b * 2]) * (1.f / g_stats[b * 2 + 1]);
    }
}

// ---------------- launch ----------------
extern "C" void kernel_launch(void* const* d_in, const int* in_sizes, int n_in,
                              void* d_out, int out_size) {
    const int*   ids  = (const int*)  d_in[0];
    const float* kc   = (const float*)d_in[1];
    const float* vc   = (const float*)d_in[2];
    const float* wte  = (const float*)d_in[3];
    const float* wpe  = (const float*)d_in[4];
    const float* l1w  = (const float*)d_in[5];
    const float* l1b  = (const float*)d_in[6];
    const float* caw  = (const float*)d_in[7];
    const float* cab  = (const float*)d_in[8];
    const float* apw  = (const float*)d_in[9];
    const float* apb  = (const float*)d_in[10];
    const float* l2w  = (const float*)d_in[11];
    const float* l2b  = (const float*)d_in[12];
    const float* fw   = (const float*)d_in[13];
    const float* fb   = (const float*)d_in[14];
    const float* pw   = (const float*)d_in[15];
    const float* pb   = (const float*)d_in[16];
    const float* lnfw = (const float*)d_in[17];
    const float* lnfb = (const float*)d_in[18];
    const float* ab   = (const float*)d_in[19];
    float* out = (float*)d_out;

    embed_kernel<<<BB, 256>>>(ids, wte, wpe, l1w, l1b);

    for (int l = 0; l < LL; l++) {
        // qkv = x @ c_attn_w  (N=3072, K=1024, 32 K-splits) -> 192 blocks
        gemv_k<32, 3 * EE, EE, BUF_QKV><<<dim3(6, QS), 256>>>(caw + (size_t)l * EE * 3 * EE);

        // flash-decode attention (one-pass, fused qkv combine): 1024 blocks
        attn_kernel<<<dim3(BB * HH, TS), 256>>>(
            kc + (size_t)l * BB * HH * TT * DD,
            vc + (size_t)l * BB * HH * TT * DD,
            cab + (size_t)l * 3 * EE,
            ab + l);

        // attn proj (combine fused into input stage) -> 64 blocks
        gemv_ctx_k<32, EE, BUF_APROJ><<<dim3(2, AS), 256>>>(apw + (size_t)l * EE * EE);

        // h += attnout + apb ; x = ln2(h)
        resid_ln_kernel<BUF_APROJ, AS><<<BB, 256>>>(apb + (size_t)l * EE,
                                                    l2w + (size_t)l * EE,
                                                    l2b + (size_t)l * EE);

        // fc = x @ fc_w  (N=4096, K=1024) -> 256 blocks
        gemv_k<32, FF, EE, BUF_FC><<<dim3(8, FS), 256>>>(fw + (size_t)l * EE * FF);

        // mlp proj = gelu(fc + fb) @ pw  (N=1024, K=4096, 64 splits) -> 128 blocks
        gemv_gelu_k<64, EE, BUF_MP><<<dim3(2, MS), 256>>>(fb + (size_t)l * FF,
                                                          pw + (size_t)l * FF * EE);

        // h += mlpout + pb ; x = ln1(h,l+1)  (or lnf at the last layer)
        const float* nlw = (l < LL - 1) ? (l1w + (size_t)(l + 1) * EE) : lnfw;
        const float* nlb = (l < LL - 1) ? (l1b + (size_t)(l + 1) * EE) : lnfb;
        resid_ln_kernel<BUF_MP, MS><<<BB, 256>>>(pb + (size_t)l * EE, nlw, nlb);
    }

    logits_kernel<<<1184, 256>>>(wte);
    softmax_stats_kernel<<<BB, 256>>>();
    softmax_norm_kernel<<<(BB * VV + 255) / 256, 256>>>(out);
}

// round 10
// speedup vs baseline: 1.5206x; 1.1723x over previous
#include <cuda_runtime.h>
#include <cuda_bf16.h>
#include <math.h>

// Problem constants
#define LL 12
#define BB 8
#define HH 16
#define DD 64
#define EE 1024
#define FF 4096
#define VV 50257
#define TT 1023
#define SS 1024

// Split configs
#define QS 64    // qkv K-splits (KC=16)
#define FS 64    // fc K-splits (KC=16)
#define AS 128   // attnproj K-splits (KC=8)
#define MS 256   // mlpproj K-splits (KC=16)
#define TS 8     // attention T splits (1024/128)

// ---------------- scratch (static device, no allocation) ----------------
__device__ __align__(16) float g_h[BB * EE];
__device__ __align__(16) float g_x[BB * EE];
__device__ __align__(16) float g_qkv[QS * BB * 3 * EE];     // 6.3MB
__device__ __align__(16) float g_qkvc[BB * 3 * EE];
__device__ __align__(16) float g_ap[BB * HH * TS * 66];     // [bh][ts][m,den,64 vals]
__device__ __align__(16) float g_aproj[AS * BB * EE];       // 4MB
__device__ __align__(16) float g_fc[FS * BB * FF];          // 8MB
__device__ __align__(16) float g_mp[MS * BB * EE];          // 8MB
__device__ __align__(16) float g_logits[BB * VV];
__device__ __align__(16) float g_stats[BB * 2];

// Scratch selection in DEVICE code only (host-side __device__ symbol = bogus addr).
#define BUF_QKV   0
#define BUF_APROJ 1
#define BUF_FC    2
#define BUF_MP    3
template<int ID>
__device__ __forceinline__ float* scratch_buf() {
    if (ID == BUF_QKV)   return g_qkv;
    if (ID == BUF_APROJ) return g_aproj;
    if (ID == BUF_FC)    return g_fc;
    return g_mp;
}

// ---------------- reductions ----------------
__device__ __forceinline__ float blockReduceSum256(float v, float* red) {
    #pragma unroll
    for (int o = 16; o; o >>= 1) v += __shfl_down_sync(0xffffffffu, v, o);
    int tid = threadIdx.x;
    if ((tid & 31) == 0) red[tid >> 5] = v;
    __syncthreads();
    if (tid == 0) {
        float s = red[0];
        #pragma unroll
        for (int i = 1; i < 8; i++) s += red[i];
        red[0] = s;
    }
    __syncthreads();
    float r = red[0];
    __syncthreads();
    return r;
}

__device__ __forceinline__ float blockReduceMax256(float v, float* red) {
    #pragma unroll
    for (int o = 16; o; o >>= 1) v = fmaxf(v, __shfl_down_sync(0xffffffffu, v, o));
    int tid = threadIdx.x;
    if ((tid & 31) == 0) red[tid >> 5] = v;
    __syncthreads();
    if (tid == 0) {
        float s = red[0];
        #pragma unroll
        for (int i = 1; i < 8; i++) s = fmaxf(s, red[i]);
        red[0] = s;
    }
    __syncthreads();
    float r = red[0];
    __syncthreads();
    return r;
}

// 1024-thread block sum (32 warps)
__device__ __forceinline__ float blockReduceSum1024(float v, float* red) {
    #pragma unroll
    for (int o = 16; o; o >>= 1) v += __shfl_down_sync(0xffffffffu, v, o);
    int tid = threadIdx.x;
    if ((tid & 31) == 0) red[tid >> 5] = v;
    __syncthreads();
    if (tid == 0) {
        float s = red[0];
        #pragma unroll
        for (int i = 1; i < 32; i++) s += red[i];
        red[0] = s;
    }
    __syncthreads();
    float r = red[0];
    __syncthreads();
    return r;
}

// ---------------- embed + ln1(layer 0) ----------------
__global__ void embed_kernel(const int* __restrict__ ids,
                             const float* __restrict__ wte,
                             const float* __restrict__ wpe,
                             const float* __restrict__ lw,
                             const float* __restrict__ lb) {
    __shared__ float red[8];
    int b = blockIdx.x, tid = threadIdx.x;   // 256 threads, one float4 each
    int id = ids[b * SS + (SS - 1)];
    float4 v = ((const float4*)(wte + (size_t)id * EE))[tid];
    float4 p = ((const float4*)(wpe + (size_t)(SS - 1) * EE))[tid];
    v.x += p.x; v.y += p.y; v.z += p.z; v.w += p.w;
    ((float4*)g_h)[b * 256 + tid] = v;
    float ls = v.x + v.y + v.z + v.w;
    float mean = blockReduceSum256(ls, red) * (1.f / EE);
    float dx = v.x - mean, dy = v.y - mean, dz = v.z - mean, dw = v.w - mean;
    ls = dx * dx + dy * dy + dz * dz + dw * dw;
    float rstd = rsqrtf(blockReduceSum256(ls, red) * (1.f / EE) + 1e-5f);
    float4 w4 = ((const float4*)lw)[tid];
    float4 b4 = ((const float4*)lb)[tid];
    float4 o;
    o.x = dx * rstd * w4.x + b4.x;
    o.y = dy * rstd * w4.y + b4.y;
    o.z = dz * rstd * w4.z + b4.z;
    o.w = dw * rstd * w4.w + b4.w;
    ((float4*)g_x)[b * 256 + tid] = o;
}

// ---------------- GEMV core: 8-batch split-K partial, float4 columns ----------------
template<int KC, int N>
__device__ __forceinline__ void gemv_core4(const float* xs,
                                           const float* __restrict__ W,
                                           float* __restrict__ part) {
    int tid = threadIdx.x;
    int k0 = blockIdx.y * KC;
    int n4 = blockIdx.x * 256 + tid;                // float4 column index
    const float4* wp = ((const float4*)W) + (size_t)k0 * (N / 4) + n4;
    float4 acc[8];
    #pragma unroll
    for (int b = 0; b < 8; b++) { acc[b].x = 0.f; acc[b].y = 0.f; acc[b].z = 0.f; acc[b].w = 0.f; }
    #pragma unroll
    for (int k = 0; k < KC; k++) {
        float4 wv = wp[(size_t)k * (N / 4)];
        #pragma unroll
        for (int b = 0; b < 8; b++) {
            float xv = xs[b * KC + k];
            acc[b].x = fmaf(xv, wv.x, acc[b].x);
            acc[b].y = fmaf(xv, wv.y, acc[b].y);
            acc[b].z = fmaf(xv, wv.z, acc[b].z);
            acc[b].w = fmaf(xv, wv.w, acc[b].w);
        }
    }
    float4* p4 = (float4*)part;
    int sp = blockIdx.y;
    #pragma unroll
    for (int b = 0; b < 8; b++)
        p4[(size_t)(sp * 8 + b) * (N / 4) + n4] = acc[b];
}

// plain: input = g_x, output = scratch_buf<DST>
template<int KC, int N, int K, int DST>
__global__ void __launch_bounds__(256) gemv_k(const float* __restrict__ W) {
    __shared__ float xs[8 * KC];
    int tid = threadIdx.x;
    int k0 = blockIdx.y * KC;
    if (tid < 8 * KC) {
        int b = tid / KC, k = tid % KC;
        xs[tid] = g_x[b * K + k0 + k];
    }
    __syncthreads();
    gemv_core4<KC, N>(xs, W, scratch_buf<DST>());
}

// gelu: input = sum of fc partials + bias, gelu'd  (K = FF)
template<int KC, int N, int DST>
__global__ void __launch_bounds__(256) gemv_gelu_k(const float* __restrict__ fcb,
                                                   const float* __restrict__ W) {
    __shared__ float xs[8 * KC];
    int tid = threadIdx.x;
    int k0 = blockIdx.y * KC;
    if (tid < 8 * KC) {
        int b = tid / KC, k = k0 + tid % KC;
        float v = fcb[k];
        #pragma unroll 16
        for (int s = 0; s < FS; s++) v += g_fc[(size_t)(s * 8 + b) * FF + k];
        float c3 = v * v * v;
        xs[tid] = 0.5f * v * (1.f + tanhf(0.7978845608028654f * (v + 0.044715f * c3)));
    }
    __syncthreads();
    gemv_core4<KC, N>(xs, W, scratch_buf<DST>());
}

// ctx: input built from attention partials (flash-decode combine), K = EE
template<int KC, int N, int DST>
__global__ void __launch_bounds__(256) gemv_ctx_k(const float* __restrict__ W) {
    __shared__ float xs[8 * KC];
    int tid = threadIdx.x;
    int k0 = blockIdx.y * KC;
    if (tid < 8 * KC) {
        int b = tid / KC;
        int kg = k0 + tid % KC;
        int head = kg >> 6, d = kg & 63;
        int bh = b * HH + head;
        const float* ap = &g_ap[(size_t)bh * TS * 66];
        float gm = -1e30f;
        #pragma unroll
        for (int ts = 0; ts < TS; ts++) gm = fmaxf(gm, ap[ts * 66]);
        float den = 0.f, val = 0.f;
        #pragma unroll
        for (int ts = 0; ts < TS; ts++) {
            float e = __expf(ap[ts * 66] - gm);
            den += ap[ts * 66 + 1] * e;
            val += ap[ts * 66 + 2 + d] * e;
        }
        xs[tid] = val / den;
    }
    __syncthreads();
    gemv_core4<KC, N>(xs, W, scratch_buf<DST>());
}

// ---------------- qkv combine: 1024 threads, 4 split-groups ----------------
__global__ void __launch_bounds__(1024) qkvc_kernel(const float* __restrict__ cab) {
    __shared__ __align__(16) float4 ps[4][256];
    int tid = threadIdx.x;
    int c = tid & 255, grp = tid >> 8;
    int c4 = blockIdx.x * 256 + c;            // 0..6143 over 24 blocks
    int b = c4 / 768, j4 = c4 - b * 768;
    float4 v; v.x = v.y = v.z = v.w = 0.f;
    #pragma unroll 4
    for (int sp = grp; sp < QS; sp += 4) {
        float4 p = ((const float4*)g_qkv)[(size_t)(sp * 8 + b) * 768 + j4];
        v.x += p.x; v.y += p.y; v.z += p.z; v.w += p.w;
    }
    ps[grp][c] = v;
    __syncthreads();
    if (grp == 0) {
        float4 bv = ((const float4*)cab)[j4];
        float4 a = ps[0][c], s1 = ps[1][c], s2 = ps[2][c], s3 = ps[3][c];
        a.x += s1.x + s2.x + s3.x + bv.x;
        a.y += s1.y + s2.y + s3.y + bv.y;
        a.z += s1.z + s2.z + s3.z + bv.z;
        a.w += s1.w + s2.w + s3.w + bv.w;
        ((float4*)g_qkvc)[c4] = a;
    }
}

// ---------------- attention: register-resident two-pass flash-decode ----------------
__global__ void __launch_bounds__(256, 2) attn_kernel(const float* __restrict__ kc,
                                                      const float* __restrict__ vc,
                                                      const float* __restrict__ abp) {
    __shared__ float gm_s[16], gd_s[16];
    __shared__ __align__(16) float gacc[16][DD];
    int tid = threadIdx.x;
    int bh = blockIdx.x;
    int b = bh >> 4, h = bh & 15;
    int ts = blockIdx.y;
    int w = tid >> 5, lane = tid & 31;
    int half = lane >> 4, sub = lane & 15;
    int g = w * 2 + half;                 // 16 lane-groups of 16

    const float* qrow = g_qkvc + b * 3 * EE + h * DD;
    float4 qv = ((const float4*)qrow)[sub];
    const float4* knp = (const float4*)(qrow + EE);
    const float4* vnp = (const float4*)(qrow + 2 * EE);
    size_t rowbase = (size_t)(b * HH + h) * TT;
    int t0 = ts * 128;
    float abias = abp[0];

    // issue all 16 independent LDG.128 before any math
    float4 kk[8], vv[8];
    #pragma unroll
    for (int j = 0; j < 8; j++) {
        int t = t0 + j * 16 + g;
        const float4* kr = (t < TT) ? (const float4*)(kc + (rowbase + t) * DD) : knp;
        kk[j] = kr[sub];
    }
    #pragma unroll
    for (int j = 0; j < 8; j++) {
        int t = t0 + j * 16 + g;
        const float4* vr = (t < TT) ? (const float4*)(vc + (rowbase + t) * DD) : vnp;
        vv[j] = vr[sub];
    }

    float p[8];
    #pragma unroll
    for (int j = 0; j < 8; j++) {
        float s = kk[j].x * qv.x + kk[j].y * qv.y + kk[j].z * qv.z + kk[j].w * qv.w;
        s += __shfl_xor_sync(0xffffffffu, s, 8);
        s += __shfl_xor_sync(0xffffffffu, s, 4);
        s += __shfl_xor_sync(0xffffffffu, s, 2);
        s += __shfl_xor_sync(0xffffffffu, s, 1);
        p[j] = s * 0.125f + abias;
    }
    float m = p[0];
    #pragma unroll
    for (int j = 1; j < 8; j++) m = fmaxf(m, p[j]);
    float den = 0.f;
    float4 acc; acc.x = acc.y = acc.z = acc.w = 0.f;
    #pragma unroll
    for (int j = 0; j < 8; j++) {
        float e = __expf(p[j] - m);
        den += e;
        acc.x = fmaf(e, vv[j].x, acc.x);
        acc.y = fmaf(e, vv[j].y, acc.y);
        acc.z = fmaf(e, vv[j].z, acc.z);
        acc.w = fmaf(e, vv[j].w, acc.w);
    }

    if (sub == 0) { gm_s[g] = m; gd_s[g] = den; }
    ((float4*)gacc[g])[sub] = acc;
    __syncthreads();

    if (tid < DD) {
        float gm = -1e30f;
        #pragma unroll
        for (int g2 = 0; g2 < 16; g2++) gm = fmaxf(gm, gm_s[g2]);
        float dd = 0.f, val = 0.f;
        #pragma unroll
        for (int g2 = 0; g2 < 16; g2++) {
            float e = __expf(gm_s[g2] - gm);
            dd += gd_s[g2] * e;
            val += gacc[g2][tid] * e;
        }
        float* ap = &g_ap[((size_t)bh * TS + ts) * 66];
        if (tid == 0) { ap[0] = gm; ap[1] = dd; }
        ap[2 + tid] = val;
    }
}

// ---------------- residual (sum split partials + bias) + layernorm -> g_x ----------------
template<int SRC, int NS>
__global__ void __launch_bounds__(1024) resid_ln_kernel(const float* __restrict__ bias,
                                                        const float* __restrict__ lw,
                                                        const float* __restrict__ lb) {
    __shared__ __align__(16) float4 ps[4][256];
    __shared__ float red[32];
    const float4* part = (const float4*)scratch_buf<SRC>();
    int b = blockIdx.x, tid = threadIdx.x;
    int c = tid & 255, grp = tid >> 8;
    float4 v; v.x = v.y = v.z = v.w = 0.f;
    #pragma unroll 8
    for (int sp = grp; sp < NS; sp += 4) {
        float4 p = part[(size_t)(sp * 8 + b) * 256 + c];
        v.x += p.x; v.y += p.y; v.z += p.z; v.w += p.w;
    }
    ps[grp][c] = v;
    __syncthreads();
    float4 hv; hv.x = hv.y = hv.z = hv.w = 0.f;
    if (grp == 0) {
        float4 h4 = ((const float4*)g_h)[b * 256 + c];
        float4 bv = ((const float4*)bias)[c];
        float4 s1 = ps[1][c], s2 = ps[2][c], s3 = ps[3][c];
        hv.x = v.x + s1.x + s2.x + s3.x + h4.x + bv.x;
        hv.y = v.y + s1.y + s2.y + s3.y + h4.y + bv.y;
        hv.z = v.z + s1.z + s2.z + s3.z + h4.z + bv.z;
        hv.w = v.w + s1.w + s2.w + s3.w + h4.w + bv.w;
        ((float4*)g_h)[b * 256 + c] = hv;
    }
    float ls = (grp == 0) ? (hv.x + hv.y + hv.z + hv.w) : 0.f;
    float mean = blockReduceSum1024(ls, red) * (1.f / EE);
    float dx = hv.x - mean, dy = hv.y - mean, dz = hv.z - mean, dw = hv.w - mean;
    ls = (grp == 0) ? (dx * dx + dy * dy + dz * dz + dw * dw) : 0.f;
    float rstd = rsqrtf(blockReduceSum1024(ls, red) * (1.f / EE) + 1e-5f);
    if (grp == 0) {
        float4 w4 = ((const float4*)lw)[c];
        float4 b4 = ((const float4*)lb)[c];
        float4 o;
        o.x = dx * rstd * w4.x + b4.x;
        o.y = dy * rstd * w4.y + b4.y;
        o.z = dz * rstd * w4.z + b4.z;
        o.w = dw * rstd * w4.w + b4.w;
        ((float4*)g_x)[b * 256 + c] = o;
    }
}

// ---------------- logits: warp per vocab row (x2), 8-batch reuse ----------------
__global__ void __launch_bounds__(256) logits_kernel(const float* __restrict__ wte) {
    __shared__ __align__(16) float4 xs[8][256];
    int tid = threadIdx.x;
    for (int i = tid; i < 2048; i += 256) {
        int b = i >> 8, j = i & 255;
        xs[b][j] = ((const float4*)g_x)[b * 256 + j];
    }
    __syncthreads();
    int w = blockIdx.x * 8 + (tid >> 5);
    int lane = tid & 31;
    int nw = gridDim.x * 8;
    for (int v0 = w * 2; v0 < VV; v0 += nw * 2) {
        int v1 = v0 + 1;
        bool has1 = (v1 < VV);
        const float4* r0 = (const float4*)(wte + (size_t)v0 * EE);
        const float4* r1 = (const float4*)(wte + (size_t)(has1 ? v1 : v0) * EE);
        float a0[8], a1[8];
        #pragma unroll
        for (int b = 0; b < 8; b++) { a0[b] = 0.f; a1[b] = 0.f; }
        #pragma unroll
        for (int i = 0; i < 8; i++) {
            int idx = lane + 32 * i;
            float4 w0 = r0[idx];
            float4 w1 = r1[idx];
            #pragma unroll
            for (int b = 0; b < 8; b++) {
                float4 xb = xs[b][idx];
                a0[b] += w0.x * xb.x + w0.y * xb.y + w0.z * xb.z + w0.w * xb.w;
                a1[b] += w1.x * xb.x + w1.y * xb.y + w1.z * xb.z + w1.w * xb.w;
            }
        }
        #pragma unroll
        for (int b = 0; b < 8; b++) {
            #pragma unroll
            for (int o = 16; o; o >>= 1) {
                a0[b] += __shfl_down_sync(0xffffffffu, a0[b], o);
                a1[b] += __shfl_down_sync(0xffffffffu, a1[b], o);
            }
        }
        if (lane == 0) {
            #pragma unroll
            for (int b = 0; b < 8; b++) {
                g_logits[(size_t)b * VV + v0] = a0[b];
                if (has1) g_logits[(size_t)b * VV + v1] = a1[b];
            }
        }
    }
}

__global__ void softmax_stats_kernel() {
    __shared__ float red[8];
    int b = blockIdx.x, tid = threadIdx.x;
    float m = -1e30f;
    for (int v = tid; v < VV; v += 256) m = fmaxf(m, g_logits[(size_t)b * VV + v]);
    m = blockReduceMax256(m, red);
    float s = 0.f;
    for (int v = tid; v < VV; v += 256) s += __expf(g_logits[(size_t)b * VV + v] - m);
    s = blockReduceSum256(s, red);
    if (tid == 0) { g_stats[b * 2] = m; g_stats[b * 2 + 1] = s; }
}

__global__ void softmax_norm_kernel(float* __restrict__ out) {
    int i = blockIdx.x * 256 + threadIdx.x;
    if (i < BB * VV) {
        int b = i / VV;
        out[i] = __expf(g_logits[i] - g_stats[b * 2]) * (1.f / g_stats[b * 2 + 1]);
    }
}

// ---------------- launch ----------------
extern "C" void kernel_launch(void* const* d_in, const int* in_sizes, int n_in,
                              void* d_out, int out_size) {
    const int*   ids  = (const int*)  d_in[0];
    const float* kc   = (const float*)d_in[1];
    const float* vc   = (const float*)d_in[2];
    const float* wte  = (const float*)d_in[3];
    const float* wpe  = (const float*)d_in[4];
    const float* l1w  = (const float*)d_in[5];
    const float* l1b  = (const float*)d_in[6];
    const float* caw  = (const float*)d_in[7];
    const float* cab  = (const float*)d_in[8];
    const float* apw  = (const float*)d_in[9];
    const float* apb  = (const float*)d_in[10];
    const float* l2w  = (const float*)d_in[11];
    const float* l2b  = (const float*)d_in[12];
    const float* fw   = (const float*)d_in[13];
    const float* fb   = (const float*)d_in[14];
    const float* pw   = (const float*)d_in[15];
    const float* pb   = (const float*)d_in[16];
    const float* lnfw = (const float*)d_in[17];
    const float* lnfb = (const float*)d_in[18];
    const float* ab   = (const float*)d_in[19];
    float* out = (float*)d_out;

    embed_kernel<<<BB, 256>>>(ids, wte, wpe, l1w, l1b);

    for (int l = 0; l < LL; l++) {
        // qkv = x @ c_attn_w  (N=3072, K=1024, 64 K-splits) -> 192 blocks
        gemv_k<16, 3 * EE, EE, BUF_QKV><<<dim3(3, QS), 256>>>(caw + (size_t)l * EE * 3 * EE);

        // combine qkv splits + bias -> g_qkvc  (24 x 1024 threads)
        qkvc_kernel<<<24, 1024>>>(cab + (size_t)l * 3 * EE);

        // flash-decode attention: 1024 blocks, register-resident two-pass
        attn_kernel<<<dim3(BB * HH, TS), 256>>>(
            kc + (size_t)l * BB * HH * TT * DD,
            vc + (size_t)l * BB * HH * TT * DD,
            ab + l);

        // attn proj (combine fused into input stage) -> 128 blocks
        gemv_ctx_k<8, EE, BUF_APROJ><<<dim3(1, AS), 256>>>(apw + (size_t)l * EE * EE);

        // h += attnout + apb ; x = ln2(h)
        resid_ln_kernel<BUF_APROJ, AS><<<BB, 1024>>>(apb + (size_t)l * EE,
                                                     l2w + (size_t)l * EE,
                                                     l2b + (size_t)l * EE);

        // fc = x @ fc_w  (N=4096, K=1024, 64 splits) -> 256 blocks
        gemv_k<16, FF, EE, BUF_FC><<<dim3(4, FS), 256>>>(fw + (size_t)l * EE * FF);

        // mlp proj = gelu(fc + fb) @ pw  (N=1024, K=4096, 256 splits) -> 256 blocks
        gemv_gelu_k<16, EE, BUF_MP><<<dim3(1, MS), 256>>>(fb + (size_t)l * FF,
                                                          pw + (size_t)l * FF * EE);

        // h += mlpout + pb ; x = ln1(h,l+1)  (or lnf at the last layer)
        const float* nlw = (l < LL - 1) ? (l1w + (size_t)(l + 1) * EE) : lnfw;
        const float* nlb = (l < LL - 1) ? (l1b + (size_t)(l + 1) * EE) : lnfb;
        resid_ln_kernel<BUF_MP, MS><<<BB, 1024>>>(pb + (size_t)l * EE, nlw, nlb);
    }

    logits_kernel<<<1184, 256>>>(wte);
    softmax_stats_kernel<<<BB, 256>>>();
    softmax_norm_kernel<<<(BB * VV + 255) / 256, 256>>>(out);
}